// round 1
// baseline (speedup 1.0000x reference)
#include <cuda_runtime.h>
#include <cuda_bf16.h>
#include <math.h>

// Problem dims (fixed by reference)
#define BATCH 8
#define SEQ   1024
#define EMB   1024
#define NHEAD 16
#define HDIM  64
#define NTOK  (BATCH * SEQ)          // 8192
#define N_QKV (3 * EMB)              // 3072
#define ROPE_ROW_OFF (1024 * 32)     // cos_tab[T] with T=1024, row stride D/2=32

// Scratch (device globals; no allocations allowed)
__device__ float g_q[BATCH * NHEAD * SEQ * HDIM];   // [B,H,T,D]
__device__ float g_k[BATCH * NHEAD * SEQ * HDIM];
__device__ float g_v[BATCH * NHEAD * SEQ * HDIM];
__device__ float g_y[NTOK * EMB];                   // attention output [B,T,E]

// ---------------------------------------------------------------------------
// Kernel 1: QKV = x @ w_qkv^T + b_qkv, fused RoPE (single-row table quirk) and
// head split into g_q/g_k/g_v [B,H,T,D].
// Tiles: 128x128x16, 256 threads, 8x8 per thread.
// ---------------------------------------------------------------------------
__global__ __launch_bounds__(256) void qkv_gemm_kernel(
    const float* __restrict__ x,       // [NTOK, EMB]
    const float* __restrict__ w,       // [N_QKV, EMB]
    const float* __restrict__ bias,    // [N_QKV]
    const float* __restrict__ cos_tab, // [4095, 32]
    const float* __restrict__ sin_tab)
{
    __shared__ float As[16 * 128];
    __shared__ float Bs[16 * 128];

    const int tid = threadIdx.x;
    const int tx = tid & 15;
    const int ty = tid >> 4;
    const int bn = blockIdx.x;   // N tile (24)
    const int bm = blockIdx.y;   // M tile (64)

    float c[8][8];
#pragma unroll
    for (int i = 0; i < 8; i++)
#pragma unroll
        for (int j = 0; j < 8; j++) c[i][j] = 0.f;

    const float* Aptr = x + (size_t)bm * 128 * EMB;
    const float* Bptr = w + (size_t)bn * 128 * EMB;

    for (int k0 = 0; k0 < EMB; k0 += 16) {
#pragma unroll
        for (int i = 0; i < 2; i++) {
            int idx = tid + i * 256;         // float4 index, 0..511
            int row = idx >> 2;              // 0..127
            int c4  = idx & 3;               // 0..3
            float4 av = *(const float4*)(Aptr + row * EMB + k0 + c4 * 4);
            As[(c4 * 4 + 0) * 128 + row] = av.x;
            As[(c4 * 4 + 1) * 128 + row] = av.y;
            As[(c4 * 4 + 2) * 128 + row] = av.z;
            As[(c4 * 4 + 3) * 128 + row] = av.w;
            float4 bv = *(const float4*)(Bptr + row * EMB + k0 + c4 * 4);
            Bs[(c4 * 4 + 0) * 128 + row] = bv.x;
            Bs[(c4 * 4 + 1) * 128 + row] = bv.y;
            Bs[(c4 * 4 + 2) * 128 + row] = bv.z;
            Bs[(c4 * 4 + 3) * 128 + row] = bv.w;
        }
        __syncthreads();
#pragma unroll
        for (int kk = 0; kk < 16; kk++) {
            float a[8], b[8];
            *(float4*)(a)     = *(const float4*)(As + kk * 128 + ty * 8);
            *(float4*)(a + 4) = *(const float4*)(As + kk * 128 + ty * 8 + 4);
            *(float4*)(b)     = *(const float4*)(Bs + kk * 128 + tx * 8);
            *(float4*)(b + 4) = *(const float4*)(Bs + kk * 128 + tx * 8 + 4);
#pragma unroll
            for (int i = 0; i < 8; i++)
#pragma unroll
                for (int j = 0; j < 8; j++) c[i][j] += a[i] * b[j];
        }
        __syncthreads();
    }

    // Epilogue: bias + RoPE + scatter to [B,H,T,D]
    const int n0  = bn * 128 + tx * 8;     // 8 consecutive qkv columns (aligned)
    const int typ = n0 >> 10;              // 0=q,1=k,2=v (no straddle: 8 | 1024)
    const int nn  = n0 & 1023;
    const int h   = nn >> 6;
    const int d0  = nn & 63;               // multiple of 8

    float bias8[8];
#pragma unroll
    for (int j = 0; j < 8; j++) bias8[j] = bias[n0 + j];

    float cosv[4], sinv[4];
    if (typ < 2) {
#pragma unroll
        for (int p = 0; p < 4; p++) {
            cosv[p] = cos_tab[ROPE_ROW_OFF + (d0 >> 1) + p];
            sinv[p] = sin_tab[ROPE_ROW_OFF + (d0 >> 1) + p];
        }
    }
    float* outp = (typ == 0) ? g_q : ((typ == 1) ? g_k : g_v);

#pragma unroll
    for (int i = 0; i < 8; i++) {
        int m  = bm * 128 + ty * 8 + i;
        int bb = m >> 10;
        int t  = m & 1023;
        float v[8];
#pragma unroll
        for (int j = 0; j < 8; j++) v[j] = c[i][j] + bias8[j];
        if (typ < 2) {
#pragma unroll
            for (int p = 0; p < 4; p++) {
                float e = v[2 * p], o = v[2 * p + 1];
                v[2 * p]     = e * cosv[p] - o * sinv[p];
                v[2 * p + 1] = e * sinv[p] + o * cosv[p];
            }
        }
        size_t base = ((size_t)(bb * NHEAD + h) * SEQ + t) * HDIM + d0;
        *(float4*)(outp + base)     = make_float4(v[0], v[1], v[2], v[3]);
        *(float4*)(outp + base + 4) = make_float4(v[4], v[5], v[6], v[7]);
    }
}

// ---------------------------------------------------------------------------
// Kernel 2: causal flash attention, fp32, BM=BN=64, D=64.
// grid = (SEQ/64, B*H), 256 threads. P reuses the K smem buffer (48KB total).
// ---------------------------------------------------------------------------
__global__ __launch_bounds__(256) void flash_attn_kernel(void)
{
    __shared__ float Qs[64 * 64];   // [d][q], pre-scaled by 1/sqrt(D)
    __shared__ float KPs[64 * 64];  // K as [d][k], then P as [q][k]
    __shared__ float Vs[64 * 64];   // [k][d]

    const int tid = threadIdx.x;
    const int tx = tid & 15;        // k-cols / d-cols * 4
    const int ty = tid >> 4;        // q-rows * 4
    const int mblock = blockIdx.x;  // 0..15
    const int bh = blockIdx.y;      // 0..127
    const float scale = 0.125f;     // 1/sqrt(64)

    const size_t head_off = (size_t)bh * SEQ * HDIM;
    const float* Qg = g_q + head_off + (size_t)mblock * 64 * HDIM;
    const float* Kg = g_k + head_off;
    const float* Vg = g_v + head_off;

    // Load Q (transposed + pre-scaled)
#pragma unroll
    for (int i = 0; i < 4; i++) {
        int idx = tid + i * 256;    // float4 idx, 0..1023
        int row = idx >> 4;         // 0..63
        int c4  = idx & 15;
        float4 qv = *(const float4*)(Qg + row * HDIM + c4 * 4);
        Qs[(c4 * 4 + 0) * 64 + row] = qv.x * scale;
        Qs[(c4 * 4 + 1) * 64 + row] = qv.y * scale;
        Qs[(c4 * 4 + 2) * 64 + row] = qv.z * scale;
        Qs[(c4 * 4 + 3) * 64 + row] = qv.w * scale;
    }

    float m_i[4], l_i[4], acc[4][4];
#pragma unroll
    for (int qi = 0; qi < 4; qi++) {
        m_i[qi] = -1e30f; l_i[qi] = 0.f;
#pragma unroll
        for (int dj = 0; dj < 4; dj++) acc[qi][dj] = 0.f;
    }

    for (int jb = 0; jb <= mblock; jb++) {
        __syncthreads();  // prior AV reads done (and Q store before 1st iter)
        const float* Kj = Kg + (size_t)jb * 64 * HDIM;
        const float* Vj = Vg + (size_t)jb * 64 * HDIM;
#pragma unroll
        for (int i = 0; i < 4; i++) {
            int idx = tid + i * 256;
            int row = idx >> 4;
            int c4  = idx & 15;
            float4 kv = *(const float4*)(Kj + row * HDIM + c4 * 4);
            KPs[(c4 * 4 + 0) * 64 + row] = kv.x;
            KPs[(c4 * 4 + 1) * 64 + row] = kv.y;
            KPs[(c4 * 4 + 2) * 64 + row] = kv.z;
            KPs[(c4 * 4 + 3) * 64 + row] = kv.w;
            *(float4*)(Vs + row * 64 + c4 * 4) = *(const float4*)(Vj + row * HDIM + c4 * 4);
        }
        __syncthreads();

        // S = Q^T K (already scaled)
        float s[4][4];
#pragma unroll
        for (int qi = 0; qi < 4; qi++)
#pragma unroll
            for (int kj = 0; kj < 4; kj++) s[qi][kj] = 0.f;
        for (int d = 0; d < 64; d++) {
            float4 qv = *(const float4*)(Qs + d * 64 + ty * 4);
            float4 kv = *(const float4*)(KPs + d * 64 + tx * 4);
            float qa[4] = {qv.x, qv.y, qv.z, qv.w};
            float ka[4] = {kv.x, kv.y, kv.z, kv.w};
#pragma unroll
            for (int qi = 0; qi < 4; qi++)
#pragma unroll
                for (int kj = 0; kj < 4; kj++) s[qi][kj] += qa[qi] * ka[kj];
        }

        // Causal mask (only needed on the diagonal block)
        if (jb == mblock) {
#pragma unroll
            for (int qi = 0; qi < 4; qi++)
#pragma unroll
                for (int kj = 0; kj < 4; kj++)
                    if ((tx * 4 + kj) > (ty * 4 + qi)) s[qi][kj] = -1e30f;
        }

        // Online softmax update
#pragma unroll
        for (int qi = 0; qi < 4; qi++) {
            float mx = fmaxf(fmaxf(s[qi][0], s[qi][1]), fmaxf(s[qi][2], s[qi][3]));
#pragma unroll
            for (int off = 1; off < 16; off <<= 1)
                mx = fmaxf(mx, __shfl_xor_sync(0xffffffffu, mx, off));
            float mnew = fmaxf(m_i[qi], mx);
            float corr = __expf(m_i[qi] - mnew);
            float rs = 0.f;
#pragma unroll
            for (int kj = 0; kj < 4; kj++) {
                float p = __expf(s[qi][kj] - mnew);
                s[qi][kj] = p;
                rs += p;
            }
#pragma unroll
            for (int off = 1; off < 16; off <<= 1)
                rs += __shfl_xor_sync(0xffffffffu, rs, off);
            l_i[qi] = l_i[qi] * corr + rs;
            m_i[qi] = mnew;
#pragma unroll
            for (int dj = 0; dj < 4; dj++) acc[qi][dj] *= corr;
        }

        __syncthreads();  // all K reads done; safe to overwrite with P
#pragma unroll
        for (int qi = 0; qi < 4; qi++)
            *(float4*)(KPs + (ty * 4 + qi) * 64 + tx * 4) =
                make_float4(s[qi][0], s[qi][1], s[qi][2], s[qi][3]);
        __syncthreads();

        // acc += P @ V
        for (int kk = 0; kk < 64; kk++) {
            float4 vv = *(const float4*)(Vs + kk * 64 + tx * 4);
            float va[4] = {vv.x, vv.y, vv.z, vv.w};
            float p[4];
#pragma unroll
            for (int qi = 0; qi < 4; qi++) p[qi] = KPs[(ty * 4 + qi) * 64 + kk];
#pragma unroll
            for (int qi = 0; qi < 4; qi++)
#pragma unroll
                for (int dj = 0; dj < 4; dj++) acc[qi][dj] += p[qi] * va[dj];
        }
    }

    // Write y [B,T,E] = [b][t][h*64+d]
    const int bb = bh >> 4;
    const int h  = bh & 15;
#pragma unroll
    for (int qi = 0; qi < 4; qi++) {
        int t = mblock * 64 + ty * 4 + qi;
        float inv = 1.f / l_i[qi];
        size_t base = ((size_t)bb * SEQ + t) * EMB + h * HDIM + tx * 4;
        *(float4*)(g_y + base) = make_float4(acc[qi][0] * inv, acc[qi][1] * inv,
                                             acc[qi][2] * inv, acc[qi][3] * inv);
    }
}

// ---------------------------------------------------------------------------
// Kernel 3: out = y @ w_out^T + b_out. Same 128x128x16 tiling.
// ---------------------------------------------------------------------------
__global__ __launch_bounds__(256) void out_gemm_kernel(
    const float* __restrict__ w,       // [EMB, EMB]
    const float* __restrict__ bias,    // [EMB]
    float* __restrict__ out)           // [NTOK, EMB]
{
    __shared__ float As[16 * 128];
    __shared__ float Bs[16 * 128];

    const int tid = threadIdx.x;
    const int tx = tid & 15;
    const int ty = tid >> 4;
    const int bn = blockIdx.x;   // 8
    const int bm = blockIdx.y;   // 64

    float c[8][8];
#pragma unroll
    for (int i = 0; i < 8; i++)
#pragma unroll
        for (int j = 0; j < 8; j++) c[i][j] = 0.f;

    const float* Aptr = g_y + (size_t)bm * 128 * EMB;
    const float* Bptr = w + (size_t)bn * 128 * EMB;

    for (int k0 = 0; k0 < EMB; k0 += 16) {
#pragma unroll
        for (int i = 0; i < 2; i++) {
            int idx = tid + i * 256;
            int row = idx >> 2;
            int c4  = idx & 3;
            float4 av = *(const float4*)(Aptr + row * EMB + k0 + c4 * 4);
            As[(c4 * 4 + 0) * 128 + row] = av.x;
            As[(c4 * 4 + 1) * 128 + row] = av.y;
            As[(c4 * 4 + 2) * 128 + row] = av.z;
            As[(c4 * 4 + 3) * 128 + row] = av.w;
            float4 bv = *(const float4*)(Bptr + row * EMB + k0 + c4 * 4);
            Bs[(c4 * 4 + 0) * 128 + row] = bv.x;
            Bs[(c4 * 4 + 1) * 128 + row] = bv.y;
            Bs[(c4 * 4 + 2) * 128 + row] = bv.z;
            Bs[(c4 * 4 + 3) * 128 + row] = bv.w;
        }
        __syncthreads();
#pragma unroll
        for (int kk = 0; kk < 16; kk++) {
            float a[8], b[8];
            *(float4*)(a)     = *(const float4*)(As + kk * 128 + ty * 8);
            *(float4*)(a + 4) = *(const float4*)(As + kk * 128 + ty * 8 + 4);
            *(float4*)(b)     = *(const float4*)(Bs + kk * 128 + tx * 8);
            *(float4*)(b + 4) = *(const float4*)(Bs + kk * 128 + tx * 8 + 4);
#pragma unroll
            for (int i = 0; i < 8; i++)
#pragma unroll
                for (int j = 0; j < 8; j++) c[i][j] += a[i] * b[j];
        }
        __syncthreads();
    }

    const int n0 = bn * 128 + tx * 8;
    float bias8[8];
#pragma unroll
    for (int j = 0; j < 8; j++) bias8[j] = bias[n0 + j];
#pragma unroll
    for (int i = 0; i < 8; i++) {
        int m = bm * 128 + ty * 8 + i;
        float v[8];
#pragma unroll
        for (int j = 0; j < 8; j++) v[j] = c[i][j] + bias8[j];
        *(float4*)(out + (size_t)m * EMB + n0)     = make_float4(v[0], v[1], v[2], v[3]);
        *(float4*)(out + (size_t)m * EMB + n0 + 4) = make_float4(v[4], v[5], v[6], v[7]);
    }
}

extern "C" void kernel_launch(void* const* d_in, const int* in_sizes, int n_in,
                              void* d_out, int out_size)
{
    const float* x       = (const float*)d_in[0];
    const float* w_qkv   = (const float*)d_in[1];
    const float* b_qkv   = (const float*)d_in[2];
    const float* w_out   = (const float*)d_in[3];
    const float* b_out   = (const float*)d_in[4];
    const float* cos_tab = (const float*)d_in[5];
    const float* sin_tab = (const float*)d_in[6];
    float* out = (float*)d_out;

    dim3 gridA(N_QKV / 128, NTOK / 128);   // 24 x 64
    qkv_gemm_kernel<<<gridA, 256>>>(x, w_qkv, b_qkv, cos_tab, sin_tab);

    dim3 gridF(SEQ / 64, BATCH * NHEAD);   // 16 x 128
    flash_attn_kernel<<<gridF, 256>>>();

    dim3 gridC(EMB / 128, NTOK / 128);     // 8 x 64
    out_gemm_kernel<<<gridC, 256>>>(w_out, b_out, out);
}

// round 2
// speedup vs baseline: 1.5438x; 1.5438x over previous
#include <cuda_runtime.h>
#include <cuda_bf16.h>
#include <math.h>

// Problem dims (fixed by reference)
#define BATCH 8
#define SEQ   1024
#define EMB   1024
#define NHEAD 16
#define HDIM  64
#define NTOK  (BATCH * SEQ)          // 8192
#define N_QKV (3 * EMB)              // 3072
#define ROPE_ROW_OFF (1024 * 32)     // cos_tab[T] with T=1024, row stride D/2=32

#define BM 128
#define BN 128
#define BK 32
#define PADK 40   // padded smem row length (bf16 elems): 80B stride -> conflict-free ldmatrix

// Scratch (device globals; no allocations allowed)
__device__ float g_q[BATCH * NHEAD * SEQ * HDIM];   // [B,H,T,D]
__device__ float g_k[BATCH * NHEAD * SEQ * HDIM];
__device__ float g_v[BATCH * NHEAD * SEQ * HDIM];
__device__ float g_y[NTOK * EMB];                   // attention output [B,T,E]

// ---------------------------------------------------------------------------
// PTX helpers
// ---------------------------------------------------------------------------
__device__ __forceinline__ void ldm_x4(unsigned* r, const void* p) {
    unsigned addr = (unsigned)__cvta_generic_to_shared(p);
    asm volatile("ldmatrix.sync.aligned.m8n8.x4.shared.b16 {%0,%1,%2,%3}, [%4];"
                 : "=r"(r[0]), "=r"(r[1]), "=r"(r[2]), "=r"(r[3]) : "r"(addr));
}

__device__ __forceinline__ void mma_bf16(float* d, const unsigned* a, const unsigned* b) {
    asm volatile("mma.sync.aligned.m16n8k16.row.col.f32.bf16.bf16.f32 "
                 "{%0,%1,%2,%3}, {%4,%5,%6,%7}, {%8,%9}, {%0,%1,%2,%3};"
                 : "+f"(d[0]), "+f"(d[1]), "+f"(d[2]), "+f"(d[3])
                 : "r"(a[0]), "r"(a[1]), "r"(a[2]), "r"(a[3]), "r"(b[0]), "r"(b[1]));
}

__device__ __forceinline__ void cvt_hilo(float v, __nv_bfloat16& hi, __nv_bfloat16& lo) {
    hi = __float2bfloat16(v);
    lo = __float2bfloat16(v - __bfloat162float(hi));
}

// Load a BMxBK fp32 tile (row stride 'ld'), split to bf16 hi/lo in smem.
// 256 threads; tile has 1024 float4s; each thread handles 4.
__device__ __forceinline__ void load_split_tile(
    const float* __restrict__ gptr, int ld, int tid,
    __nv_bfloat16* __restrict__ shi, __nv_bfloat16* __restrict__ slo)
{
#pragma unroll
    for (int i = 0; i < 4; i++) {
        int fid = tid + i * 256;            // 0..1023
        int row = fid >> 3;                 // 0..127
        int c4  = fid & 7;                  // 0..7
        float4 v = *(const float4*)(gptr + (size_t)row * ld + c4 * 4);
        __nv_bfloat16 h0, l0, h1, l1, h2, l2, h3, l3;
        cvt_hilo(v.x, h0, l0); cvt_hilo(v.y, h1, l1);
        cvt_hilo(v.z, h2, l2); cvt_hilo(v.w, h3, l3);
        int off = row * PADK + c4 * 4;
        *(__nv_bfloat162*)(shi + off)     = __nv_bfloat162(h0, h1);
        *(__nv_bfloat162*)(shi + off + 2) = __nv_bfloat162(h2, h3);
        *(__nv_bfloat162*)(slo + off)     = __nv_bfloat162(l0, l1);
        *(__nv_bfloat162*)(slo + off + 2) = __nv_bfloat162(l2, l3);
    }
}

// ---------------------------------------------------------------------------
// Kernel 1: QKV = x @ w_qkv^T + b_qkv (bf16x3 tensor core), fused RoPE
// (single-row table quirk) + head split into g_q/g_k/g_v [B,H,T,D].
// Block 128x128xK32, 256 threads = 8 warps (2 M x 4 N), warp tile 64x32.
// ---------------------------------------------------------------------------
__global__ __launch_bounds__(256, 1) void qkv_gemm_kernel(
    const float* __restrict__ x,       // [NTOK, EMB]
    const float* __restrict__ w,       // [N_QKV, EMB]
    const float* __restrict__ bias,    // [N_QKV]
    const float* __restrict__ cos_tab,
    const float* __restrict__ sin_tab)
{
    __shared__ __nv_bfloat16 sAhi[BM * PADK], sAlo[BM * PADK];
    __shared__ __nv_bfloat16 sBhi[BN * PADK], sBlo[BN * PADK];

    const int tid = threadIdx.x;
    const int lane = tid & 31;
    const int warp = tid >> 5;
    const int wm = warp & 1;     // 0..1
    const int wn = warp >> 1;    // 0..3
    const int bn = blockIdx.x;
    const int bm = blockIdx.y;

    float d[4][4][4];
#pragma unroll
    for (int mt = 0; mt < 4; mt++)
#pragma unroll
        for (int nt = 0; nt < 4; nt++)
#pragma unroll
            for (int r = 0; r < 4; r++) d[mt][nt][r] = 0.f;

    const float* Aptr = x + (size_t)bm * BM * EMB;
    const float* Bptr = w + (size_t)bn * BN * EMB;

    const int arow = lane & 15;
    const int acolo = (lane >> 4) * 8;
    const int brow = (lane & 7) + ((lane >> 4) & 1) * 8;
    const int bcolo = ((lane >> 3) & 1) * 8;

    for (int k0 = 0; k0 < EMB; k0 += BK) {
        load_split_tile(Aptr + k0, EMB, tid, sAhi, sAlo);
        load_split_tile(Bptr + k0, EMB, tid, sBhi, sBlo);
        __syncthreads();

#pragma unroll
        for (int ks = 0; ks < BK; ks += 16) {
            unsigned ahi[4][4], alo[4][4], bhi[4][2], blo[4][2];
#pragma unroll
            for (int mt = 0; mt < 4; mt++) {
                int r = (wm * 64 + mt * 16 + arow) * PADK + ks + acolo;
                ldm_x4(ahi[mt], &sAhi[r]);
                ldm_x4(alo[mt], &sAlo[r]);
            }
#pragma unroll
            for (int np = 0; np < 2; np++) {
                int r = (wn * 32 + np * 16 + brow) * PADK + ks + bcolo;
                unsigned t4[4];
                ldm_x4(t4, &sBhi[r]);
                bhi[np*2][0] = t4[0]; bhi[np*2][1] = t4[1];
                bhi[np*2+1][0] = t4[2]; bhi[np*2+1][1] = t4[3];
                ldm_x4(t4, &sBlo[r]);
                blo[np*2][0] = t4[0]; blo[np*2][1] = t4[1];
                blo[np*2+1][0] = t4[2]; blo[np*2+1][1] = t4[3];
            }
#pragma unroll
            for (int mt = 0; mt < 4; mt++)
#pragma unroll
                for (int nt = 0; nt < 4; nt++) {
                    mma_bf16(d[mt][nt], ahi[mt], bhi[nt]);
                    mma_bf16(d[mt][nt], ahi[mt], blo[nt]);
                    mma_bf16(d[mt][nt], alo[mt], bhi[nt]);
                }
        }
        __syncthreads();
    }

    // Epilogue: bias + RoPE + scatter to [B,H,T,D]
    const int lr = lane >> 2;          // 0..7
    const int lc = (lane & 3) * 2;     // even col
#pragma unroll
    for (int mt = 0; mt < 4; mt++) {
#pragma unroll
        for (int half = 0; half < 2; half++) {
            int m = bm * BM + wm * 64 + mt * 16 + lr + half * 8;
            int bb = m >> 10;
            int t  = m & 1023;
#pragma unroll
            for (int nt = 0; nt < 4; nt++) {
                int n = bn * BN + wn * 32 + nt * 8 + lc;
                float v0 = d[mt][nt][half * 2 + 0] + bias[n];
                float v1 = d[mt][nt][half * 2 + 1] + bias[n + 1];
                int typ = n >> 10;                 // 0=q,1=k,2=v (no straddle)
                int nn = n & 1023;
                int h  = nn >> 6;
                int d0 = nn & 63;                  // even
                if (typ < 2) {
                    float cv = cos_tab[ROPE_ROW_OFF + (d0 >> 1)];
                    float sv = sin_tab[ROPE_ROW_OFF + (d0 >> 1)];
                    float e = v0, o = v1;
                    v0 = e * cv - o * sv;
                    v1 = e * sv + o * cv;
                }
                float* outp = (typ == 0) ? g_q : ((typ == 1) ? g_k : g_v);
                size_t base = ((size_t)(bb * NHEAD + h) * SEQ + t) * HDIM + d0;
                *(float2*)(outp + base) = make_float2(v0, v1);
            }
        }
    }
}

// ---------------------------------------------------------------------------
// Kernel 2: causal flash attention, fp32, BM=BN=64, D=64. (unchanged)
// ---------------------------------------------------------------------------
__global__ __launch_bounds__(256) void flash_attn_kernel(void)
{
    __shared__ float Qs[64 * 64];   // [d][q], pre-scaled
    __shared__ float KPs[64 * 64];  // K as [d][k], then P as [q][k]
    __shared__ float Vs[64 * 64];   // [k][d]

    const int tid = threadIdx.x;
    const int tx = tid & 15;
    const int ty = tid >> 4;
    const int mblock = blockIdx.x;
    const int bh = blockIdx.y;
    const float scale = 0.125f;

    const size_t head_off = (size_t)bh * SEQ * HDIM;
    const float* Qg = g_q + head_off + (size_t)mblock * 64 * HDIM;
    const float* Kg = g_k + head_off;
    const float* Vg = g_v + head_off;

#pragma unroll
    for (int i = 0; i < 4; i++) {
        int idx = tid + i * 256;
        int row = idx >> 4;
        int c4  = idx & 15;
        float4 qv = *(const float4*)(Qg + row * HDIM + c4 * 4);
        Qs[(c4 * 4 + 0) * 64 + row] = qv.x * scale;
        Qs[(c4 * 4 + 1) * 64 + row] = qv.y * scale;
        Qs[(c4 * 4 + 2) * 64 + row] = qv.z * scale;
        Qs[(c4 * 4 + 3) * 64 + row] = qv.w * scale;
    }

    float m_i[4], l_i[4], acc[4][4];
#pragma unroll
    for (int qi = 0; qi < 4; qi++) {
        m_i[qi] = -1e30f; l_i[qi] = 0.f;
#pragma unroll
        for (int dj = 0; dj < 4; dj++) acc[qi][dj] = 0.f;
    }

    for (int jb = 0; jb <= mblock; jb++) {
        __syncthreads();
        const float* Kj = Kg + (size_t)jb * 64 * HDIM;
        const float* Vj = Vg + (size_t)jb * 64 * HDIM;
#pragma unroll
        for (int i = 0; i < 4; i++) {
            int idx = tid + i * 256;
            int row = idx >> 4;
            int c4  = idx & 15;
            float4 kv = *(const float4*)(Kj + row * HDIM + c4 * 4);
            KPs[(c4 * 4 + 0) * 64 + row] = kv.x;
            KPs[(c4 * 4 + 1) * 64 + row] = kv.y;
            KPs[(c4 * 4 + 2) * 64 + row] = kv.z;
            KPs[(c4 * 4 + 3) * 64 + row] = kv.w;
            *(float4*)(Vs + row * 64 + c4 * 4) = *(const float4*)(Vj + row * HDIM + c4 * 4);
        }
        __syncthreads();

        float s[4][4];
#pragma unroll
        for (int qi = 0; qi < 4; qi++)
#pragma unroll
            for (int kj = 0; kj < 4; kj++) s[qi][kj] = 0.f;
        for (int dd = 0; dd < 64; dd++) {
            float4 qv = *(const float4*)(Qs + dd * 64 + ty * 4);
            float4 kv = *(const float4*)(KPs + dd * 64 + tx * 4);
            float qa[4] = {qv.x, qv.y, qv.z, qv.w};
            float ka[4] = {kv.x, kv.y, kv.z, kv.w};
#pragma unroll
            for (int qi = 0; qi < 4; qi++)
#pragma unroll
                for (int kj = 0; kj < 4; kj++) s[qi][kj] += qa[qi] * ka[kj];
        }

        if (jb == mblock) {
#pragma unroll
            for (int qi = 0; qi < 4; qi++)
#pragma unroll
                for (int kj = 0; kj < 4; kj++)
                    if ((tx * 4 + kj) > (ty * 4 + qi)) s[qi][kj] = -1e30f;
        }

#pragma unroll
        for (int qi = 0; qi < 4; qi++) {
            float mx = fmaxf(fmaxf(s[qi][0], s[qi][1]), fmaxf(s[qi][2], s[qi][3]));
#pragma unroll
            for (int off = 1; off < 16; off <<= 1)
                mx = fmaxf(mx, __shfl_xor_sync(0xffffffffu, mx, off));
            float mnew = fmaxf(m_i[qi], mx);
            float corr = __expf(m_i[qi] - mnew);
            float rs = 0.f;
#pragma unroll
            for (int kj = 0; kj < 4; kj++) {
                float p = __expf(s[qi][kj] - mnew);
                s[qi][kj] = p;
                rs += p;
            }
#pragma unroll
            for (int off = 1; off < 16; off <<= 1)
                rs += __shfl_xor_sync(0xffffffffu, rs, off);
            l_i[qi] = l_i[qi] * corr + rs;
            m_i[qi] = mnew;
#pragma unroll
            for (int dj = 0; dj < 4; dj++) acc[qi][dj] *= corr;
        }

        __syncthreads();
#pragma unroll
        for (int qi = 0; qi < 4; qi++)
            *(float4*)(KPs + (ty * 4 + qi) * 64 + tx * 4) =
                make_float4(s[qi][0], s[qi][1], s[qi][2], s[qi][3]);
        __syncthreads();

        for (int kk = 0; kk < 64; kk++) {
            float4 vv = *(const float4*)(Vs + kk * 64 + tx * 4);
            float va[4] = {vv.x, vv.y, vv.z, vv.w};
            float p[4];
#pragma unroll
            for (int qi = 0; qi < 4; qi++) p[qi] = KPs[(ty * 4 + qi) * 64 + kk];
#pragma unroll
            for (int qi = 0; qi < 4; qi++)
#pragma unroll
                for (int dj = 0; dj < 4; dj++) acc[qi][dj] += p[qi] * va[dj];
        }
    }

    const int bb = bh >> 4;
    const int h  = bh & 15;
#pragma unroll
    for (int qi = 0; qi < 4; qi++) {
        int t = mblock * 64 + ty * 4 + qi;
        float inv = 1.f / l_i[qi];
        size_t base = ((size_t)bb * SEQ + t) * EMB + h * HDIM + tx * 4;
        *(float4*)(g_y + base) = make_float4(acc[qi][0] * inv, acc[qi][1] * inv,
                                             acc[qi][2] * inv, acc[qi][3] * inv);
    }
}

// ---------------------------------------------------------------------------
// Kernel 3: out = y @ w_out^T + b_out (bf16x3 tensor core)
// ---------------------------------------------------------------------------
__global__ __launch_bounds__(256, 1) void out_gemm_kernel(
    const float* __restrict__ w,       // [EMB, EMB]
    const float* __restrict__ bias,    // [EMB]
    float* __restrict__ out)           // [NTOK, EMB]
{
    __shared__ __nv_bfloat16 sAhi[BM * PADK], sAlo[BM * PADK];
    __shared__ __nv_bfloat16 sBhi[BN * PADK], sBlo[BN * PADK];

    const int tid = threadIdx.x;
    const int lane = tid & 31;
    const int warp = tid >> 5;
    const int wm = warp & 1;
    const int wn = warp >> 1;
    const int bn = blockIdx.x;
    const int bm = blockIdx.y;

    float d[4][4][4];
#pragma unroll
    for (int mt = 0; mt < 4; mt++)
#pragma unroll
        for (int nt = 0; nt < 4; nt++)
#pragma unroll
            for (int r = 0; r < 4; r++) d[mt][nt][r] = 0.f;

    const float* Aptr = g_y + (size_t)bm * BM * EMB;
    const float* Bptr = w + (size_t)bn * BN * EMB;

    const int arow = lane & 15;
    const int acolo = (lane >> 4) * 8;
    const int brow = (lane & 7) + ((lane >> 4) & 1) * 8;
    const int bcolo = ((lane >> 3) & 1) * 8;

    for (int k0 = 0; k0 < EMB; k0 += BK) {
        load_split_tile(Aptr + k0, EMB, tid, sAhi, sAlo);
        load_split_tile(Bptr + k0, EMB, tid, sBhi, sBlo);
        __syncthreads();

#pragma unroll
        for (int ks = 0; ks < BK; ks += 16) {
            unsigned ahi[4][4], alo[4][4], bhi[4][2], blo[4][2];
#pragma unroll
            for (int mt = 0; mt < 4; mt++) {
                int r = (wm * 64 + mt * 16 + arow) * PADK + ks + acolo;
                ldm_x4(ahi[mt], &sAhi[r]);
                ldm_x4(alo[mt], &sAlo[r]);
            }
#pragma unroll
            for (int np = 0; np < 2; np++) {
                int r = (wn * 32 + np * 16 + brow) * PADK + ks + bcolo;
                unsigned t4[4];
                ldm_x4(t4, &sBhi[r]);
                bhi[np*2][0] = t4[0]; bhi[np*2][1] = t4[1];
                bhi[np*2+1][0] = t4[2]; bhi[np*2+1][1] = t4[3];
                ldm_x4(t4, &sBlo[r]);
                blo[np*2][0] = t4[0]; blo[np*2][1] = t4[1];
                blo[np*2+1][0] = t4[2]; blo[np*2+1][1] = t4[3];
            }
#pragma unroll
            for (int mt = 0; mt < 4; mt++)
#pragma unroll
                for (int nt = 0; nt < 4; nt++) {
                    mma_bf16(d[mt][nt], ahi[mt], bhi[nt]);
                    mma_bf16(d[mt][nt], ahi[mt], blo[nt]);
                    mma_bf16(d[mt][nt], alo[mt], bhi[nt]);
                }
        }
        __syncthreads();
    }

    const int lr = lane >> 2;
    const int lc = (lane & 3) * 2;
#pragma unroll
    for (int mt = 0; mt < 4; mt++) {
#pragma unroll
        for (int half = 0; half < 2; half++) {
            int m = bm * BM + wm * 64 + mt * 16 + lr + half * 8;
#pragma unroll
            for (int nt = 0; nt < 4; nt++) {
                int n = bn * BN + wn * 32 + nt * 8 + lc;
                float v0 = d[mt][nt][half * 2 + 0] + bias[n];
                float v1 = d[mt][nt][half * 2 + 1] + bias[n + 1];
                *(float2*)(out + (size_t)m * EMB + n) = make_float2(v0, v1);
            }
        }
    }
}

extern "C" void kernel_launch(void* const* d_in, const int* in_sizes, int n_in,
                              void* d_out, int out_size)
{
    const float* x       = (const float*)d_in[0];
    const float* w_qkv   = (const float*)d_in[1];
    const float* b_qkv   = (const float*)d_in[2];
    const float* w_out   = (const float*)d_in[3];
    const float* b_out   = (const float*)d_in[4];
    const float* cos_tab = (const float*)d_in[5];
    const float* sin_tab = (const float*)d_in[6];
    float* out = (float*)d_out;

    dim3 gridA(N_QKV / BN, NTOK / BM);     // 24 x 64
    qkv_gemm_kernel<<<gridA, 256>>>(x, w_qkv, b_qkv, cos_tab, sin_tab);

    dim3 gridF(SEQ / 64, BATCH * NHEAD);   // 16 x 128
    flash_attn_kernel<<<gridF, 256>>>();

    dim3 gridC(EMB / BN, NTOK / BM);       // 8 x 64
    out_gemm_kernel<<<gridC, 256>>>(w_out, b_out, out);
}

// round 3
// speedup vs baseline: 2.5765x; 1.6689x over previous
#include <cuda_runtime.h>
#include <cuda_bf16.h>
#include <math.h>

// Problem dims (fixed by reference)
#define BATCH 8
#define SEQ   1024
#define EMB   1024
#define NHEAD 16
#define HDIM  64
#define NTOK  (BATCH * SEQ)          // 8192
#define N_QKV (3 * EMB)              // 3072
#define ROPE_ROW_OFF (1024 * 32)     // cos_tab[T] quirk: single row at position 1024

#define BM 128
#define BN 128
#define BK 32
#define PADK 40   // smem row stride (bf16): 80B -> conflict-free ldmatrix, 16B-aligned chunks

// ---------------------------------------------------------------------------
// Scratch (device globals; no allocations allowed)
// ---------------------------------------------------------------------------
__device__ __nv_bfloat16 g_xhi[NTOK * EMB],  g_xlo[NTOK * EMB];
__device__ __nv_bfloat16 g_wqkvhi[N_QKV * EMB], g_wqkvlo[N_QKV * EMB];
__device__ __nv_bfloat16 g_wouthi[EMB * EMB],   g_woutlo[EMB * EMB];
__device__ __nv_bfloat16 g_qhi[BATCH * NHEAD * SEQ * HDIM], g_qlo[BATCH * NHEAD * SEQ * HDIM]; // [B,H,T,D]
__device__ __nv_bfloat16 g_khi[BATCH * NHEAD * SEQ * HDIM], g_klo[BATCH * NHEAD * SEQ * HDIM]; // [B,H,T,D]
__device__ __nv_bfloat16 g_vhi[BATCH * NHEAD * HDIM * SEQ], g_vlo[BATCH * NHEAD * HDIM * SEQ]; // [B,H,D,T]
__device__ __nv_bfloat16 g_yhi[NTOK * EMB],  g_ylo[NTOK * EMB];                                 // [B,T,E]

// ---------------------------------------------------------------------------
// PTX helpers
// ---------------------------------------------------------------------------
__device__ __forceinline__ void ldm_x4(unsigned* r, const void* p) {
    unsigned addr = (unsigned)__cvta_generic_to_shared(p);
    asm volatile("ldmatrix.sync.aligned.m8n8.x4.shared.b16 {%0,%1,%2,%3}, [%4];"
                 : "=r"(r[0]), "=r"(r[1]), "=r"(r[2]), "=r"(r[3]) : "r"(addr));
}

__device__ __forceinline__ void mma_bf16(float* d, const unsigned* a, const unsigned* b) {
    asm volatile("mma.sync.aligned.m16n8k16.row.col.f32.bf16.bf16.f32 "
                 "{%0,%1,%2,%3}, {%4,%5,%6,%7}, {%8,%9}, {%0,%1,%2,%3};"
                 : "+f"(d[0]), "+f"(d[1]), "+f"(d[2]), "+f"(d[3])
                 : "r"(a[0]), "r"(a[1]), "r"(a[2]), "r"(a[3]), "r"(b[0]), "r"(b[1]));
}

__device__ __forceinline__ void cvt_hilo(float v, __nv_bfloat16& hi, __nv_bfloat16& lo) {
    hi = __float2bfloat16(v);
    lo = __float2bfloat16(v - __bfloat162float(hi));
}

// pack two floats' hi parts (and lo parts) into bf16x2 registers
__device__ __forceinline__ void split_pack(float a, float b, unsigned& hi, unsigned& lo) {
    __nv_bfloat16 ah, al, bh, bl;
    cvt_hilo(a, ah, al);
    cvt_hilo(b, bh, bl);
    __nv_bfloat162 h2(ah, bh), l2(al, bl);
    hi = *reinterpret_cast<unsigned*>(&h2);
    lo = *reinterpret_cast<unsigned*>(&l2);
}

// ---------------------------------------------------------------------------
// Conversion kernel: fp32 -> bf16 hi/lo (grid-stride over float4)
// ---------------------------------------------------------------------------
__global__ __launch_bounds__(256) void split_kernel(
    const float* __restrict__ src, __nv_bfloat16* __restrict__ hi,
    __nv_bfloat16* __restrict__ lo, int n4)
{
    int i = blockIdx.x * blockDim.x + threadIdx.x;
    if (i >= n4) return;
    float4 v = ((const float4*)src)[i];
    __nv_bfloat16 h0, l0, h1, l1, h2, l2, h3, l3;
    cvt_hilo(v.x, h0, l0); cvt_hilo(v.y, h1, l1);
    cvt_hilo(v.z, h2, l2); cvt_hilo(v.w, h3, l3);
    ((__nv_bfloat162*)hi)[2 * i]     = __nv_bfloat162(h0, h1);
    ((__nv_bfloat162*)hi)[2 * i + 1] = __nv_bfloat162(h2, h3);
    ((__nv_bfloat162*)lo)[2 * i]     = __nv_bfloat162(l0, l1);
    ((__nv_bfloat162*)lo)[2 * i + 1] = __nv_bfloat162(l2, l3);
}

// ---------------------------------------------------------------------------
// Kernel 1: QKV GEMM (bf16x3), inputs pre-split. Fused bias + RoPE; emits
// q/k as bf16 hi/lo [B,H,T,D] and v as bf16 hi/lo [B,H,D,T] (pre-transposed).
// 128x128xK32 tiles, 256 thr = 8 warps (2M x 4N), register-prefetch pipeline.
// ---------------------------------------------------------------------------
__global__ __launch_bounds__(256, 1) void qkv_gemm_kernel(
    const float* __restrict__ bias,
    const float* __restrict__ cos_tab,
    const float* __restrict__ sin_tab)
{
    __shared__ __nv_bfloat16 sAhi[BM * PADK], sAlo[BM * PADK];
    __shared__ __nv_bfloat16 sBhi[BN * PADK], sBlo[BN * PADK];

    const int tid = threadIdx.x;
    const int lane = tid & 31;
    const int warp = tid >> 5;
    const int wm = warp & 1;
    const int wn = warp >> 1;
    const int bn = blockIdx.x;
    const int bm = blockIdx.y;

    float d[4][4][4];
#pragma unroll
    for (int mt = 0; mt < 4; mt++)
#pragma unroll
        for (int nt = 0; nt < 4; nt++)
#pragma unroll
            for (int r = 0; r < 4; r++) d[mt][nt][r] = 0.f;

    const __nv_bfloat16* Ah = g_xhi + (size_t)bm * BM * EMB;
    const __nv_bfloat16* Al = g_xlo + (size_t)bm * BM * EMB;
    const __nv_bfloat16* Bh = g_wqkvhi + (size_t)bn * BN * EMB;
    const __nv_bfloat16* Bl = g_wqkvlo + (size_t)bn * BN * EMB;

    const int prow = tid >> 2;        // 0..63 (x2 via i)
    const int pc   = tid & 3;

    uint4 rAh[2], rAl[2], rBh[2], rBl[2];
#pragma unroll
    for (int i = 0; i < 2; i++) {
        size_t off = (size_t)(prow + i * 64) * EMB + pc * 8;
        rAh[i] = *(const uint4*)(Ah + off);
        rAl[i] = *(const uint4*)(Al + off);
        rBh[i] = *(const uint4*)(Bh + off);
        rBl[i] = *(const uint4*)(Bl + off);
    }

    const int arow = lane & 15;
    const int acolo = (lane >> 4) * 8;
    const int brow = (lane & 7) + ((lane >> 4) & 1) * 8;
    const int bcolo = ((lane >> 3) & 1) * 8;

    for (int k0 = 0; k0 < EMB; k0 += BK) {
#pragma unroll
        for (int i = 0; i < 2; i++) {
            int so = (prow + i * 64) * PADK + pc * 8;
            *(uint4*)(sAhi + so) = rAh[i];
            *(uint4*)(sAlo + so) = rAl[i];
            *(uint4*)(sBhi + so) = rBh[i];
            *(uint4*)(sBlo + so) = rBl[i];
        }
        __syncthreads();
        if (k0 + BK < EMB) {
#pragma unroll
            for (int i = 0; i < 2; i++) {
                size_t off = (size_t)(prow + i * 64) * EMB + (k0 + BK) + pc * 8;
                rAh[i] = *(const uint4*)(Ah + off);
                rAl[i] = *(const uint4*)(Al + off);
                rBh[i] = *(const uint4*)(Bh + off);
                rBl[i] = *(const uint4*)(Bl + off);
            }
        }
#pragma unroll
        for (int ks = 0; ks < BK; ks += 16) {
            unsigned ahi[4][4], alo[4][4], bhi[4][2], blo[4][2];
#pragma unroll
            for (int mt = 0; mt < 4; mt++) {
                int r = (wm * 64 + mt * 16 + arow) * PADK + ks + acolo;
                ldm_x4(ahi[mt], &sAhi[r]);
                ldm_x4(alo[mt], &sAlo[r]);
            }
#pragma unroll
            for (int np = 0; np < 2; np++) {
                int r = (wn * 32 + np * 16 + brow) * PADK + ks + bcolo;
                unsigned t4[4];
                ldm_x4(t4, &sBhi[r]);
                bhi[np*2][0] = t4[0]; bhi[np*2][1] = t4[1];
                bhi[np*2+1][0] = t4[2]; bhi[np*2+1][1] = t4[3];
                ldm_x4(t4, &sBlo[r]);
                blo[np*2][0] = t4[0]; blo[np*2][1] = t4[1];
                blo[np*2+1][0] = t4[2]; blo[np*2+1][1] = t4[3];
            }
#pragma unroll
            for (int mt = 0; mt < 4; mt++)
#pragma unroll
                for (int nt = 0; nt < 4; nt++) {
                    mma_bf16(d[mt][nt], ahi[mt], bhi[nt]);
                    mma_bf16(d[mt][nt], ahi[mt], blo[nt]);
                    mma_bf16(d[mt][nt], alo[mt], bhi[nt]);
                }
        }
        __syncthreads();
    }

    // Epilogue: bias + RoPE + split hi/lo + scatter
    const int lr = lane >> 2;
    const int lc = (lane & 3) * 2;
#pragma unroll
    for (int mt = 0; mt < 4; mt++) {
#pragma unroll
        for (int half = 0; half < 2; half++) {
            int m = bm * BM + wm * 64 + mt * 16 + lr + half * 8;
            int bb = m >> 10;
            int t  = m & 1023;
#pragma unroll
            for (int nt = 0; nt < 4; nt++) {
                int n = bn * BN + wn * 32 + nt * 8 + lc;
                float v0 = d[mt][nt][half * 2 + 0] + bias[n];
                float v1 = d[mt][nt][half * 2 + 1] + bias[n + 1];
                int typ = n >> 10;      // 0=q,1=k,2=v
                int nn = n & 1023;
                int h  = nn >> 6;
                int d0 = nn & 63;       // even
                if (typ < 2) {
                    float cv = cos_tab[ROPE_ROW_OFF + (d0 >> 1)];
                    float sv = sin_tab[ROPE_ROW_OFF + (d0 >> 1)];
                    float e = v0, o = v1;
                    v0 = e * cv - o * sv;
                    v1 = e * sv + o * cv;
                }
                __nv_bfloat16 h0, l0, h1, l1;
                cvt_hilo(v0, h0, l0);
                cvt_hilo(v1, h1, l1);
                if (typ == 2) {
                    // transposed layout [B,H,D,T]
                    size_t base = ((size_t)(bb * NHEAD + h) * HDIM + d0) * SEQ + t;
                    g_vhi[base] = h0; g_vhi[base + SEQ] = h1;
                    g_vlo[base] = l0; g_vlo[base + SEQ] = l1;
                } else {
                    size_t base = ((size_t)(bb * NHEAD + h) * SEQ + t) * HDIM + d0;
                    __nv_bfloat16* ph = (typ == 0) ? g_qhi : g_khi;
                    __nv_bfloat16* pl = (typ == 0) ? g_qlo : g_klo;
                    *(__nv_bfloat162*)(ph + base) = __nv_bfloat162(h0, h1);
                    *(__nv_bfloat162*)(pl + base) = __nv_bfloat162(l0, l1);
                }
            }
        }
    }
}

// ---------------------------------------------------------------------------
// Kernel 2: tensor-core causal flash attention (bf16x3), 64q block, 4 warps.
// Dynamic smem: Q/K/V hi+lo tiles, 64x72 each (55296 B).
// ---------------------------------------------------------------------------
#define ATT_PAD 72
#define ATT_TILE (64 * ATT_PAD)

__global__ __launch_bounds__(128) void flash_attn_kernel(void)
{
    extern __shared__ __nv_bfloat16 sm[];
    __nv_bfloat16* QH = sm;
    __nv_bfloat16* QL = sm + ATT_TILE;
    __nv_bfloat16* KH = sm + 2 * ATT_TILE;
    __nv_bfloat16* KL = sm + 3 * ATT_TILE;
    __nv_bfloat16* VH = sm + 4 * ATT_TILE;
    __nv_bfloat16* VL = sm + 5 * ATT_TILE;

    const int tid = threadIdx.x;
    const int lane = tid & 31;
    const int warp = tid >> 5;
    const int mblock = blockIdx.x;   // 0..15
    const int bh = blockIdx.y;       // 0..127

    const size_t qoff = (size_t)bh * SEQ * HDIM + (size_t)mblock * 64 * HDIM;
#pragma unroll
    for (int i = 0; i < 4; i++) {
        int id = tid + i * 128;
        int row = id >> 3;
        int c = id & 7;
        int so = row * ATT_PAD + c * 8;
        *(uint4*)(QH + so) = *(const uint4*)(g_qhi + qoff + row * HDIM + c * 8);
        *(uint4*)(QL + so) = *(const uint4*)(g_qlo + qoff + row * HDIM + c * 8);
    }

    float m0 = -1e30f, m1 = -1e30f, l0 = 0.f, l1 = 0.f;
    float o[8][4];
#pragma unroll
    for (int nt = 0; nt < 8; nt++)
#pragma unroll
        for (int j = 0; j < 4; j++) o[nt][j] = 0.f;

    const int arow = lane & 15;
    const int acolo = (lane >> 4) * 8;
    const int brow = (lane & 7) + ((lane >> 4) & 1) * 8;
    const int bcolo = ((lane >> 3) & 1) * 8;

    for (int jb = 0; jb <= mblock; jb++) {
        const size_t koff = (size_t)bh * SEQ * HDIM + (size_t)jb * 64 * HDIM;
        const size_t voff = (size_t)bh * HDIM * SEQ + (size_t)jb * 64;
#pragma unroll
        for (int i = 0; i < 4; i++) {
            int id = tid + i * 128;
            int row = id >> 3;
            int c = id & 7;
            int so = row * ATT_PAD + c * 8;
            *(uint4*)(KH + so) = *(const uint4*)(g_khi + koff + row * HDIM + c * 8);
            *(uint4*)(KL + so) = *(const uint4*)(g_klo + koff + row * HDIM + c * 8);
            *(uint4*)(VH + so) = *(const uint4*)(g_vhi + voff + (size_t)row * SEQ + c * 8);
            *(uint4*)(VL + so) = *(const uint4*)(g_vlo + voff + (size_t)row * SEQ + c * 8);
        }
        __syncthreads();

        // S = Q K^T (bf16x3)
        float s[8][4];
#pragma unroll
        for (int nt = 0; nt < 8; nt++)
#pragma unroll
            for (int j = 0; j < 4; j++) s[nt][j] = 0.f;

#pragma unroll
        for (int ks = 0; ks < 4; ks++) {
            unsigned ah[4], al[4], bh_[8][2], bl_[8][2];
            ldm_x4(ah, &QH[(warp * 16 + arow) * ATT_PAD + ks * 16 + acolo]);
            ldm_x4(al, &QL[(warp * 16 + arow) * ATT_PAD + ks * 16 + acolo]);
#pragma unroll
            for (int np = 0; np < 4; np++) {
                unsigned t4[4];
                ldm_x4(t4, &KH[(np * 16 + brow) * ATT_PAD + ks * 16 + bcolo]);
                bh_[np*2][0] = t4[0]; bh_[np*2][1] = t4[1];
                bh_[np*2+1][0] = t4[2]; bh_[np*2+1][1] = t4[3];
                ldm_x4(t4, &KL[(np * 16 + brow) * ATT_PAD + ks * 16 + bcolo]);
                bl_[np*2][0] = t4[0]; bl_[np*2][1] = t4[1];
                bl_[np*2+1][0] = t4[2]; bl_[np*2+1][1] = t4[3];
            }
#pragma unroll
            for (int nt = 0; nt < 8; nt++) {
                mma_bf16(s[nt], ah, bh_[nt]);
                mma_bf16(s[nt], ah, bl_[nt]);
                mma_bf16(s[nt], al, bh_[nt]);
            }
        }

        // scale + causal mask
#pragma unroll
        for (int nt = 0; nt < 8; nt++)
#pragma unroll
            for (int j = 0; j < 4; j++) s[nt][j] *= 0.125f;

        if (jb == mblock) {
            int qr0 = warp * 16 + (lane >> 2);
            int qr1 = qr0 + 8;
#pragma unroll
            for (int nt = 0; nt < 8; nt++) {
                int kc = nt * 8 + 2 * (lane & 3);
                if (kc     > qr0) s[nt][0] = -1e30f;
                if (kc + 1 > qr0) s[nt][1] = -1e30f;
                if (kc     > qr1) s[nt][2] = -1e30f;
                if (kc + 1 > qr1) s[nt][3] = -1e30f;
            }
        }

        // online softmax (rows qr0 via c0/c1, qr1 via c2/c3)
        float rmax0 = -1e30f, rmax1 = -1e30f;
#pragma unroll
        for (int nt = 0; nt < 8; nt++) {
            rmax0 = fmaxf(rmax0, fmaxf(s[nt][0], s[nt][1]));
            rmax1 = fmaxf(rmax1, fmaxf(s[nt][2], s[nt][3]));
        }
#pragma unroll
        for (int off = 1; off < 4; off <<= 1) {
            rmax0 = fmaxf(rmax0, __shfl_xor_sync(0xffffffffu, rmax0, off));
            rmax1 = fmaxf(rmax1, __shfl_xor_sync(0xffffffffu, rmax1, off));
        }
        float mn0 = fmaxf(m0, rmax0), mn1 = fmaxf(m1, rmax1);
        float c0 = __expf(m0 - mn0), c1 = __expf(m1 - mn1);
        float rs0 = 0.f, rs1 = 0.f;
#pragma unroll
        for (int nt = 0; nt < 8; nt++) {
            s[nt][0] = __expf(s[nt][0] - mn0);
            s[nt][1] = __expf(s[nt][1] - mn0);
            s[nt][2] = __expf(s[nt][2] - mn1);
            s[nt][3] = __expf(s[nt][3] - mn1);
            rs0 += s[nt][0] + s[nt][1];
            rs1 += s[nt][2] + s[nt][3];
        }
#pragma unroll
        for (int off = 1; off < 4; off <<= 1) {
            rs0 += __shfl_xor_sync(0xffffffffu, rs0, off);
            rs1 += __shfl_xor_sync(0xffffffffu, rs1, off);
        }
        l0 = l0 * c0 + rs0;
        l1 = l1 * c1 + rs1;
        m0 = mn0; m1 = mn1;
#pragma unroll
        for (int nt = 0; nt < 8; nt++) {
            o[nt][0] *= c0; o[nt][1] *= c0;
            o[nt][2] *= c1; o[nt][3] *= c1;
        }

        // O += P V (bf16x3); P fragments built from s accumulators
#pragma unroll
        for (int ks = 0; ks < 4; ks++) {
            unsigned aph[4], apl[4];
            split_pack(s[2*ks][0],   s[2*ks][1],   aph[0], apl[0]);
            split_pack(s[2*ks][2],   s[2*ks][3],   aph[1], apl[1]);
            split_pack(s[2*ks+1][0], s[2*ks+1][1], aph[2], apl[2]);
            split_pack(s[2*ks+1][2], s[2*ks+1][3], aph[3], apl[3]);
            unsigned bvh[8][2], bvl[8][2];
#pragma unroll
            for (int np = 0; np < 4; np++) {
                unsigned t4[4];
                ldm_x4(t4, &VH[(np * 16 + brow) * ATT_PAD + ks * 16 + bcolo]);
                bvh[np*2][0] = t4[0]; bvh[np*2][1] = t4[1];
                bvh[np*2+1][0] = t4[2]; bvh[np*2+1][1] = t4[3];
                ldm_x4(t4, &VL[(np * 16 + brow) * ATT_PAD + ks * 16 + bcolo]);
                bvl[np*2][0] = t4[0]; bvl[np*2][1] = t4[1];
                bvl[np*2+1][0] = t4[2]; bvl[np*2+1][1] = t4[3];
            }
#pragma unroll
            for (int nt = 0; nt < 8; nt++) {
                mma_bf16(o[nt], aph, bvh[nt]);
                mma_bf16(o[nt], aph, bvl[nt]);
                mma_bf16(o[nt], apl, bvh[nt]);
            }
        }
        __syncthreads();
    }

    // Epilogue: y = O / l, stored as bf16 hi/lo [B,T,E]
    const float inv0 = 1.f / l0, inv1 = 1.f / l1;
    const int bb = bh >> 4;
    const int h = bh & 15;
    const int t0 = mblock * 64 + warp * 16 + (lane >> 2);
    const int t1 = t0 + 8;
#pragma unroll
    for (int nt = 0; nt < 8; nt++) {
        int e = h * HDIM + nt * 8 + 2 * (lane & 3);
        unsigned hi, lo;
        split_pack(o[nt][0] * inv0, o[nt][1] * inv0, hi, lo);
        *(unsigned*)(g_yhi + (size_t)(bb * SEQ + t0) * EMB + e) = hi;
        *(unsigned*)(g_ylo + (size_t)(bb * SEQ + t0) * EMB + e) = lo;
        split_pack(o[nt][2] * inv1, o[nt][3] * inv1, hi, lo);
        *(unsigned*)(g_yhi + (size_t)(bb * SEQ + t1) * EMB + e) = hi;
        *(unsigned*)(g_ylo + (size_t)(bb * SEQ + t1) * EMB + e) = lo;
    }
}

// ---------------------------------------------------------------------------
// Kernel 3: out = y @ w_out^T + b_out (bf16x3, pre-split inputs, prefetch)
// ---------------------------------------------------------------------------
__global__ __launch_bounds__(256, 1) void out_gemm_kernel(
    const float* __restrict__ bias,
    float* __restrict__ out)
{
    __shared__ __nv_bfloat16 sAhi[BM * PADK], sAlo[BM * PADK];
    __shared__ __nv_bfloat16 sBhi[BN * PADK], sBlo[BN * PADK];

    const int tid = threadIdx.x;
    const int lane = tid & 31;
    const int warp = tid >> 5;
    const int wm = warp & 1;
    const int wn = warp >> 1;
    const int bn = blockIdx.x;
    const int bm = blockIdx.y;

    float d[4][4][4];
#pragma unroll
    for (int mt = 0; mt < 4; mt++)
#pragma unroll
        for (int nt = 0; nt < 4; nt++)
#pragma unroll
            for (int r = 0; r < 4; r++) d[mt][nt][r] = 0.f;

    const __nv_bfloat16* Ah = g_yhi + (size_t)bm * BM * EMB;
    const __nv_bfloat16* Al = g_ylo + (size_t)bm * BM * EMB;
    const __nv_bfloat16* Bh = g_wouthi + (size_t)bn * BN * EMB;
    const __nv_bfloat16* Bl = g_woutlo + (size_t)bn * BN * EMB;

    const int prow = tid >> 2;
    const int pc   = tid & 3;

    uint4 rAh[2], rAl[2], rBh[2], rBl[2];
#pragma unroll
    for (int i = 0; i < 2; i++) {
        size_t off = (size_t)(prow + i * 64) * EMB + pc * 8;
        rAh[i] = *(const uint4*)(Ah + off);
        rAl[i] = *(const uint4*)(Al + off);
        rBh[i] = *(const uint4*)(Bh + off);
        rBl[i] = *(const uint4*)(Bl + off);
    }

    const int arow = lane & 15;
    const int acolo = (lane >> 4) * 8;
    const int brow = (lane & 7) + ((lane >> 4) & 1) * 8;
    const int bcolo = ((lane >> 3) & 1) * 8;

    for (int k0 = 0; k0 < EMB; k0 += BK) {
#pragma unroll
        for (int i = 0; i < 2; i++) {
            int so = (prow + i * 64) * PADK + pc * 8;
            *(uint4*)(sAhi + so) = rAh[i];
            *(uint4*)(sAlo + so) = rAl[i];
            *(uint4*)(sBhi + so) = rBh[i];
            *(uint4*)(sBlo + so) = rBl[i];
        }
        __syncthreads();
        if (k0 + BK < EMB) {
#pragma unroll
            for (int i = 0; i < 2; i++) {
                size_t off = (size_t)(prow + i * 64) * EMB + (k0 + BK) + pc * 8;
                rAh[i] = *(const uint4*)(Ah + off);
                rAl[i] = *(const uint4*)(Al + off);
                rBh[i] = *(const uint4*)(Bh + off);
                rBl[i] = *(const uint4*)(Bl + off);
            }
        }
#pragma unroll
        for (int ks = 0; ks < BK; ks += 16) {
            unsigned ahi[4][4], alo[4][4], bhi[4][2], blo[4][2];
#pragma unroll
            for (int mt = 0; mt < 4; mt++) {
                int r = (wm * 64 + mt * 16 + arow) * PADK + ks + acolo;
                ldm_x4(ahi[mt], &sAhi[r]);
                ldm_x4(alo[mt], &sAlo[r]);
            }
#pragma unroll
            for (int np = 0; np < 2; np++) {
                int r = (wn * 32 + np * 16 + brow) * PADK + ks + bcolo;
                unsigned t4[4];
                ldm_x4(t4, &sBhi[r]);
                bhi[np*2][0] = t4[0]; bhi[np*2][1] = t4[1];
                bhi[np*2+1][0] = t4[2]; bhi[np*2+1][1] = t4[3];
                ldm_x4(t4, &sBlo[r]);
                blo[np*2][0] = t4[0]; blo[np*2][1] = t4[1];
                blo[np*2+1][0] = t4[2]; blo[np*2+1][1] = t4[3];
            }
#pragma unroll
            for (int mt = 0; mt < 4; mt++)
#pragma unroll
                for (int nt = 0; nt < 4; nt++) {
                    mma_bf16(d[mt][nt], ahi[mt], bhi[nt]);
                    mma_bf16(d[mt][nt], ahi[mt], blo[nt]);
                    mma_bf16(d[mt][nt], alo[mt], bhi[nt]);
                }
        }
        __syncthreads();
    }

    const int lr = lane >> 2;
    const int lc = (lane & 3) * 2;
#pragma unroll
    for (int mt = 0; mt < 4; mt++) {
#pragma unroll
        for (int half = 0; half < 2; half++) {
            int m = bm * BM + wm * 64 + mt * 16 + lr + half * 8;
#pragma unroll
            for (int nt = 0; nt < 4; nt++) {
                int n = bn * BN + wn * 32 + nt * 8 + lc;
                float v0 = d[mt][nt][half * 2 + 0] + bias[n];
                float v1 = d[mt][nt][half * 2 + 1] + bias[n + 1];
                *(float2*)(out + (size_t)m * EMB + n) = make_float2(v0, v1);
            }
        }
    }
}

// ---------------------------------------------------------------------------
extern "C" void kernel_launch(void* const* d_in, const int* in_sizes, int n_in,
                              void* d_out, int out_size)
{
    const float* x       = (const float*)d_in[0];
    const float* w_qkv   = (const float*)d_in[1];
    const float* b_qkv   = (const float*)d_in[2];
    const float* w_out   = (const float*)d_in[3];
    const float* b_out   = (const float*)d_in[4];
    const float* cos_tab = (const float*)d_in[5];
    const float* sin_tab = (const float*)d_in[6];
    float* out = (float*)d_out;

    // attention kernel needs 55296 B dynamic smem
    static_assert(6 * ATT_TILE * sizeof(__nv_bfloat16) == 55296, "smem size");
    cudaFuncSetAttribute(flash_attn_kernel,
                         cudaFuncAttributeMaxDynamicSharedMemorySize, 55296);

    // pre-split inputs to bf16 hi/lo
    __nv_bfloat16 *xhi_p, *xlo_p, *wqh_p, *wql_p, *woh_p, *wol_p;
    cudaGetSymbolAddress((void**)&xhi_p, g_xhi);
    cudaGetSymbolAddress((void**)&xlo_p, g_xlo);
    cudaGetSymbolAddress((void**)&wqh_p, g_wqkvhi);
    cudaGetSymbolAddress((void**)&wql_p, g_wqkvlo);
    cudaGetSymbolAddress((void**)&woh_p, g_wouthi);
    cudaGetSymbolAddress((void**)&wol_p, g_woutlo);

    int n4x = NTOK * EMB / 4;
    split_kernel<<<(n4x + 255) / 256, 256>>>(x, xhi_p, xlo_p, n4x);
    int n4q = N_QKV * EMB / 4;
    split_kernel<<<(n4q + 255) / 256, 256>>>(w_qkv, wqh_p, wql_p, n4q);
    int n4o = EMB * EMB / 4;
    split_kernel<<<(n4o + 255) / 256, 256>>>(w_out, woh_p, wol_p, n4o);

    dim3 gridA(N_QKV / BN, NTOK / BM);     // 24 x 64
    qkv_gemm_kernel<<<gridA, 256>>>(b_qkv, cos_tab, sin_tab);

    dim3 gridF(SEQ / 64, BATCH * NHEAD);   // 16 x 128
    flash_attn_kernel<<<gridF, 128, 55296>>>();

    dim3 gridC(EMB / BN, NTOK / BM);       // 8 x 64
    out_gemm_kernel<<<gridC, 256>>>(b_out, out);
}